// round 8
// baseline (speedup 1.0000x reference)
#include <cuda_runtime.h>
#include <cuda_bf16.h>
#include <math.h>

// QuantumLayer as a multilinear polynomial (exact identity):
//   out_o(x) = T[o] . (1,cos x0,sin x0) x ... x (1,cos x3,sin x3)
// T (4 x 3^4, batch-constant) built from 81 circuit samples at {0,pi/2,pi}^4
// + inverse 3x3 Vandermonde per axis.
// ONE persistent kernel: every block builds T redundantly into its own shared
// memory (no inter-block sync/spin), then grabs 512-element tiles from a
// global atomic counter. Single graph node removes the measured ~4us
// second-launch overhead. R8 fix vs R7: build phase loops strided for 256
// threads (R7 kept 512-thread guards -> 40% of T never written).
// Hot path: 4 sincos + 320 FMA/element (85% of the FFMA-3reg structural cap).

#define GRID_BLOCKS 592
#define TILE_ELEMS  512   // 256 threads x 2 elements

__device__ unsigned int g_tile_ctr;   // zero-init; reset by last block each run
__device__ unsigned int g_done_ctr;

__global__ __launch_bounds__(256, 4) void qlayer_persistent(
    const float* __restrict__ x, const float* __restrict__ w,
    float* __restrict__ out, int B)
{
    __shared__ __align__(16) float shTf[432];  // [o][k0][k1][k2][k3 padded to 4]
    __shared__ float bufA[324], bufB[324];
    __shared__ float wc[12], wsn[12];
    __shared__ unsigned int s_tile;
    const int t = threadIdx.x;

    // ================= Per-block T build (all blocks, redundant) =================
    if (t < 12) {
        float s, c;
        __sincosf(0.5f * w[t], &s, &c);
        wc[t] = c; wsn[t] = s;
    }
    __syncthreads();

    if (t < 81) {
        // half-angle cos/sin of sample angles {0, pi/2, pi}
        const float hc[3] = {1.0f, 0.70710678118654752f, 0.0f};
        const float hs[3] = {0.0f, 0.70710678118654752f, 1.0f};
        const int a[4] = {t / 27, (t / 9) % 3, (t / 3) % 3, t % 3};

        // Post-input-RX state directly as a product:
        //   amp_j = (-i)^popcount(j) * prod_q (bit(3-q)? hs : hc)
        float vr[16], vi[16];
#pragma unroll
        for (int j = 0; j < 16; j++) {
            float m = 1.0f;
#pragma unroll
            for (int q = 0; q < 4; q++)
                m *= ((j >> (3 - q)) & 1) ? hs[a[q]] : hc[a[q]];
            const int pc = __popc(j) & 3;
            vr[j] = (pc == 0) ? m : ((pc == 2) ? -m : 0.0f);
            vi[j] = (pc == 1) ? -m : ((pc == 3) ? m : 0.0f);
        }

        // 3 layers: RX(w) x4 then CNOT ring.
#pragma unroll
        for (int l = 0; l < 3; l++) {
#pragma unroll
            for (int q = 0; q < 4; q++) {
                const float cq = wc[l * 4 + q], sq = wsn[l * 4 + q];
                const int bit = 1 << (3 - q);
#pragma unroll
                for (int i = 0; i < 16; i++) {
                    if (i & bit) continue;
                    const int i1 = i | bit;
                    float ar = vr[i], ai = vi[i], br = vr[i1], bi = vi[i1];
                    vr[i]  = cq * ar + sq * bi;  vi[i]  = cq * ai - sq * br;
                    vr[i1] = cq * br + sq * ai;  vi[i1] = cq * bi - sq * ar;
                }
            }
#pragma unroll
            for (int q = 0; q < 4; q++) {
                const int pcb = 3 - q;
                const int ptb = 3 - ((q + 1) & 3);
#pragma unroll
                for (int i = 0; i < 16; i++) {
                    if (((i >> pcb) & 1) == 0) continue;
                    if ((i >> ptb) & 1) continue;
                    const int i2 = i | (1 << ptb);
                    float tr = vr[i], ti = vi[i];
                    vr[i] = vr[i2]; vi[i] = vi[i2];
                    vr[i2] = tr;    vi[i2] = ti;
                }
            }
        }

        float p[16];
#pragma unroll
        for (int i = 0; i < 16; i++) p[i] = vr[i] * vr[i] + vi[i] * vi[i];
#pragma unroll
        for (int q = 0; q < 4; q++) {
            float s = 0.0f;
#pragma unroll
            for (int i = 0; i < 16; i++)
                s += ((i >> (3 - q)) & 1) ? -p[i] : p[i];
            bufA[q * 81 + t] = s;
        }
    }
    __syncthreads();

    // Inverse Vandermonde for basis (1, cos, sin) at samples {0, pi/2, pi}:
    //   c0 = (s0+s2)/2 ; c1 = (s0-s2)/2 ; c2 = s1 - (s0+s2)/2
    // STRIDED for 256 threads (324 and 432 work items).
    {
        const float Vi[3][3] = {{0.5f, 0.0f, 0.5f},
                                {0.5f, 0.0f, -0.5f},
                                {-0.5f, 1.0f, -0.5f}};
        const int WST[4] = {27, 9, 3, 1};
        float* src = bufA;
        float* dst = bufB;
        for (int ax = 3; ax >= 0; ax--) {
            for (int e2 = t; e2 < 324; e2 += 256) {
                const int o = e2 / 81, e = e2 % 81;
                const int ws2 = WST[ax];
                const int k = (e / ws2) % 3;
                const int eb = e - k * ws2;
                const float* s = src + o * 81;
                dst[e2] = Vi[k][0] * s[eb] + Vi[k][1] * s[eb + ws2] + Vi[k][2] * s[eb + 2 * ws2];
            }
            __syncthreads();
            float* tmp = src; src = dst; dst = tmp;
        }
        // 4 passes -> result in src; expand to padded layout.
        for (int e2 = t; e2 < 432; e2 += 256) {
            const int o = e2 / 108, r = e2 % 108, k012 = r / 4, c = r % 4;
            shTf[e2] = (c < 3) ? src[o * 81 + k012 * 3 + c] : 0.0f;
        }
    }
    __syncthreads();

    const float4* __restrict__ shT = (const float4*)shTf;  // [o*27+k0*9+k1*3+k2]
    const unsigned int ntiles = (unsigned int)((B + TILE_ELEMS - 1) / TILE_ELEMS);
    const float4* __restrict__ x4 = (const float4*)x;
    float4* __restrict__ o4 = (float4*)out;

    // ================= Persistent tile loop (dynamic, self-balancing) =================
    for (;;) {
        if (t == 0) s_tile = atomicAdd(&g_tile_ctr, 1u);
        __syncthreads();
        const unsigned int tile = s_tile;
        __syncthreads();           // protect s_tile before next overwrite
        if (tile >= ntiles) break;

        const long long e0 = (long long)tile * TILE_ELEMS + t * 2;
        if (e0 < B) {
            float C[2][4], S[2][4];
#pragma unroll
            for (int el = 0; el < 2; el++) {
                long long ei = e0 + el; if (ei >= B) ei = B - 1;
                float4 v = x4[ei];
                __sincosf(v.x, &S[el][0], &C[el][0]);
                __sincosf(v.y, &S[el][1], &C[el][1]);
                __sincosf(v.z, &S[el][2], &C[el][2]);
                __sincosf(v.w, &S[el][3], &C[el][3]);
            }

            float outv[2][4];
#pragma unroll
            for (int o = 0; o < 4; o++) {
                float acc[2];
#pragma unroll
                for (int k0 = 0; k0 < 3; k0++) {
                    float Aacc[2];
#pragma unroll
                    for (int k1 = 0; k1 < 3; k1++) {
                        float Bacc[2];
#pragma unroll
                        for (int k2 = 0; k2 < 3; k2++) {
                            const float4 tq = shT[o * 27 + k0 * 9 + k1 * 3 + k2];
#pragma unroll
                            for (int el = 0; el < 2; el++) {
                                float D = fmaf(tq.z, S[el][3], fmaf(tq.y, C[el][3], tq.x));
                                if (k2 == 0)      Bacc[el] = D;
                                else if (k2 == 1) Bacc[el] = fmaf(C[el][2], D, Bacc[el]);
                                else              Bacc[el] = fmaf(S[el][2], D, Bacc[el]);
                            }
                        }
#pragma unroll
                        for (int el = 0; el < 2; el++) {
                            if (k1 == 0)      Aacc[el] = Bacc[el];
                            else if (k1 == 1) Aacc[el] = fmaf(C[el][1], Bacc[el], Aacc[el]);
                            else              Aacc[el] = fmaf(S[el][1], Bacc[el], Aacc[el]);
                        }
                    }
#pragma unroll
                    for (int el = 0; el < 2; el++) {
                        if (k0 == 0)      acc[el] = Aacc[el];
                        else if (k0 == 1) acc[el] = fmaf(C[el][0], Aacc[el], acc[el]);
                        else              acc[el] = fmaf(S[el][0], Aacc[el], acc[el]);
                    }
                }
#pragma unroll
                for (int el = 0; el < 2; el++) outv[el][o] = acc[el];
            }

#pragma unroll
            for (int el = 0; el < 2; el++) {
                long long ei = e0 + el;
                if (ei < B) o4[ei] = make_float4(outv[el][0], outv[el][1], outv[el][2], outv[el][3]);
            }
        }
    }

    // ================= Reset counters for next graph replay =================
    if (t == 0) {
        __threadfence();
        unsigned int v = atomicAdd(&g_done_ctr, 1u);
        if (v == gridDim.x - 1) {
            g_tile_ctr = 0u;
            g_done_ctr = 0u;
            __threadfence();
        }
    }
}

// ---------------------------------------------------------------------------
extern "C" void kernel_launch(void* const* d_in, const int* in_sizes, int n_in,
                              void* d_out, int out_size) {
    const float* xp = (const float*)d_in[0];
    const float* wp = (const float*)d_in[1];
    int sx = in_sizes[0];
    if (n_in >= 2 && in_sizes[0] == 12 && in_sizes[1] != 12) {
        xp = (const float*)d_in[1];
        wp = (const float*)d_in[0];
        sx = in_sizes[1];
    }
    const int B = sx / 4;

    qlayer_persistent<<<GRID_BLOCKS, 256>>>(xp, wp, (float*)d_out, B);
}

// round 9
// speedup vs baseline: 1.0920x; 1.0920x over previous
#include <cuda_runtime.h>
#include <cuda_bf16.h>
#include <math.h>

// QuantumLayer as a multilinear polynomial (exact identity):
//   out_o(x) = T[o] . (1,cos x0,sin x0) x ... x (1,cos x3,sin x3)
// T (4 x 3^4, batch-constant) = circuit sampled at {0,pi/2,pi}^4 + inverse 3x3
// Vandermonde per axis. Two kernels under PDL; build_T triggers launch
// completion AT ITS START so qlayer's launch + T-independent prolog (x loads,
// sincos) overlap build_T's execution; the T read is gated by
// cudaGridDependencySynchronize (full primary completion + visibility).
// Hot path: 4 sincos + 320 FMA/element (~85% of the FFMA-3reg chip floor).

__device__ __align__(16) float g_T[432];  // [o][k0][k1][k2][k3 padded to 4]

// ---------------------------------------------------------------------------
// Kernel 1: build T from weights (12 floats). One block, 512 threads.
// ---------------------------------------------------------------------------
__global__ void build_T_kernel(const float* __restrict__ w) {
    // Let the PDL secondary start launching immediately: everything the
    // secondary does before cudaGridDependencySynchronize() is T-independent.
    cudaTriggerProgrammaticLaunchCompletion();

    __shared__ float bufA[324], bufB[324];
    __shared__ float wc[12], ws[12];
    const int t = threadIdx.x;

    if (t < 12) {
        float s, c;
        __sincosf(0.5f * w[t], &s, &c);
        wc[t] = c; ws[t] = s;
    }
    __syncthreads();

    if (t < 81) {
        // half-angle cos/sin of sample angles {0, pi/2, pi}
        const float hc[3] = {1.0f, 0.70710678118654752f, 0.0f};
        const float hs[3] = {0.0f, 0.70710678118654752f, 1.0f};
        const int a[4] = {t / 27, (t / 9) % 3, (t / 3) % 3, t % 3};

        // Post-input-RX state directly as a product:
        //   amp_j = (-i)^popcount(j) * prod_q (bit(3-q)? hs : hc)
        float vr[16], vi[16];
#pragma unroll
        for (int j = 0; j < 16; j++) {
            float m = 1.0f;
#pragma unroll
            for (int q = 0; q < 4; q++)
                m *= ((j >> (3 - q)) & 1) ? hs[a[q]] : hc[a[q]];
            const int pc = __popc(j) & 3;
            vr[j] = (pc == 0) ? m : ((pc == 2) ? -m : 0.0f);
            vi[j] = (pc == 1) ? -m : ((pc == 3) ? m : 0.0f);
        }

        // 3 layers: RX(w) x4 then CNOT ring.
#pragma unroll
        for (int l = 0; l < 3; l++) {
#pragma unroll
            for (int q = 0; q < 4; q++) {
                const float cq = wc[l * 4 + q], sq = ws[l * 4 + q];
                const int bit = 1 << (3 - q);
#pragma unroll
                for (int i = 0; i < 16; i++) {
                    if (i & bit) continue;
                    const int i1 = i | bit;
                    float ar = vr[i], ai = vi[i], br = vr[i1], bi = vi[i1];
                    vr[i]  = cq * ar + sq * bi;  vi[i]  = cq * ai - sq * br;
                    vr[i1] = cq * br + sq * ai;  vi[i1] = cq * bi - sq * ar;
                }
            }
#pragma unroll
            for (int q = 0; q < 4; q++) {
                const int pcb = 3 - q;
                const int ptb = 3 - ((q + 1) & 3);
#pragma unroll
                for (int i = 0; i < 16; i++) {
                    if (((i >> pcb) & 1) == 0) continue;
                    if ((i >> ptb) & 1) continue;
                    const int i2 = i | (1 << ptb);
                    float tr = vr[i], ti = vi[i];
                    vr[i] = vr[i2]; vi[i] = vi[i2];
                    vr[i2] = tr;    vi[i2] = ti;
                }
            }
        }

        float p[16];
#pragma unroll
        for (int i = 0; i < 16; i++) p[i] = vr[i] * vr[i] + vi[i] * vi[i];
#pragma unroll
        for (int q = 0; q < 4; q++) {
            float s = 0.0f;
#pragma unroll
            for (int i = 0; i < 16; i++)
                s += ((i >> (3 - q)) & 1) ? -p[i] : p[i];
            bufA[q * 81 + t] = s;
        }
    }
    __syncthreads();

    // Inverse Vandermonde for basis (1, cos, sin) at samples {0, pi/2, pi}:
    //   c0 = (s0+s2)/2 ; c1 = (s0-s2)/2 ; c2 = s1 - (s0+s2)/2
    const float Vi[3][3] = {{0.5f, 0.0f, 0.5f},
                            {0.5f, 0.0f, -0.5f},
                            {-0.5f, 1.0f, -0.5f}};
    const int WST[4] = {27, 9, 3, 1};
    float* src = bufA;
    float* dst = bufB;
    for (int ax = 3; ax >= 0; ax--) {
        if (t < 324) {
            const int o = t / 81, e = t % 81;
            const int ws2 = WST[ax];
            const int k = (e / ws2) % 3;
            const int eb = e - k * ws2;
            const float* s = src + o * 81;
            dst[t] = Vi[k][0] * s[eb] + Vi[k][1] * s[eb + ws2] + Vi[k][2] * s[eb + 2 * ws2];
        }
        __syncthreads();
        float* tmp = src; src = dst; dst = tmp;
    }

    if (t < 432) {
        const int o = t / 108, r = t % 108, k012 = r / 4, c = r % 4;
        g_T[t] = (c < 3) ? src[o * 81 + k012 * 3 + c] : 0.0f;
    }
}

// ---------------------------------------------------------------------------
// Kernel 2: 2 elements/thread, PDL-gated T read. 320 FMA/element Horner.
// ---------------------------------------------------------------------------
__global__ __launch_bounds__(256, 4) void qlayer_kernel(
    const float* __restrict__ x, float* __restrict__ out, int B)
{
    __shared__ __align__(16) float4 shT[108];   // [o*27 + k0*9 + k1*3 + k2], .xyz = k3
    const int t = threadIdx.x;

    const long long e0 = ((long long)blockIdx.x * 256 + t) * 2;
    const bool active = (e0 < B);

    // Prolog (independent of T): overlaps with build_T under PDL.
    float C[2][4], S[2][4];
    if (active) {
        const float4* __restrict__ x4 = (const float4*)x;
#pragma unroll
        for (int el = 0; el < 2; el++) {
            long long ei = e0 + el; if (ei >= B) ei = B - 1;
            float4 v = x4[ei];
            __sincosf(v.x, &S[el][0], &C[el][0]);
            __sincosf(v.y, &S[el][1], &C[el][1]);
            __sincosf(v.z, &S[el][2], &C[el][2]);
            __sincosf(v.w, &S[el][3], &C[el][3]);
        }
    }

    // Gate: wait for build_T completion + memory visibility (no-op if plain-launched).
    cudaGridDependencySynchronize();

    if (t < 108) shT[t] = __ldcg(((const float4*)g_T) + t);
    __syncthreads();

    if (active) {
        float outv[2][4];  // [el][o]
#pragma unroll
        for (int o = 0; o < 4; o++) {
            float acc[2];
#pragma unroll
            for (int k0 = 0; k0 < 3; k0++) {
                float Aacc[2];
#pragma unroll
                for (int k1 = 0; k1 < 3; k1++) {
                    float Bacc[2];
#pragma unroll
                    for (int k2 = 0; k2 < 3; k2++) {
                        const float4 tq = shT[o * 27 + k0 * 9 + k1 * 3 + k2];
#pragma unroll
                        for (int el = 0; el < 2; el++) {
                            float D = fmaf(tq.z, S[el][3], fmaf(tq.y, C[el][3], tq.x));
                            if (k2 == 0)      Bacc[el] = D;
                            else if (k2 == 1) Bacc[el] = fmaf(C[el][2], D, Bacc[el]);
                            else              Bacc[el] = fmaf(S[el][2], D, Bacc[el]);
                        }
                    }
#pragma unroll
                    for (int el = 0; el < 2; el++) {
                        if (k1 == 0)      Aacc[el] = Bacc[el];
                        else if (k1 == 1) Aacc[el] = fmaf(C[el][1], Bacc[el], Aacc[el]);
                        else              Aacc[el] = fmaf(S[el][1], Bacc[el], Aacc[el]);
                    }
                }
#pragma unroll
                for (int el = 0; el < 2; el++) {
                    if (k0 == 0)      acc[el] = Aacc[el];
                    else if (k0 == 1) acc[el] = fmaf(C[el][0], Aacc[el], acc[el]);
                    else              acc[el] = fmaf(S[el][0], Aacc[el], acc[el]);
                }
            }
#pragma unroll
            for (int el = 0; el < 2; el++) outv[el][o] = acc[el];
        }

        float4* __restrict__ o4 = (float4*)out;
#pragma unroll
        for (int el = 0; el < 2; el++) {
            long long ei = e0 + el;
            if (ei < B) o4[ei] = make_float4(outv[el][0], outv[el][1], outv[el][2], outv[el][3]);
        }
    }
}

// ---------------------------------------------------------------------------
extern "C" void kernel_launch(void* const* d_in, const int* in_sizes, int n_in,
                              void* d_out, int out_size) {
    const float* xp = (const float*)d_in[0];
    const float* wp = (const float*)d_in[1];
    int sx = in_sizes[0];
    if (n_in >= 2 && in_sizes[0] == 12 && in_sizes[1] != 12) {
        xp = (const float*)d_in[1];
        wp = (const float*)d_in[0];
        sx = in_sizes[1];
    }
    const int B = sx / 4;

    build_T_kernel<<<1, 512>>>(wp);

    const int elems_per_block = 256 * 2;
    const int grid = (B + elems_per_block - 1) / elems_per_block;

    // PDL: secondary may launch as soon as build_T triggers (at its start);
    // the in-kernel cudaGridDependencySynchronize() gates the T read.
    cudaLaunchConfig_t cfg = {};
    cfg.gridDim = dim3((unsigned)grid);
    cfg.blockDim = dim3(256);
    cfg.dynamicSmemBytes = 0;
    cfg.stream = 0;
    cudaLaunchAttribute attr[1];
    attr[0].id = cudaLaunchAttributeProgrammaticStreamSerialization;
    attr[0].val.programmaticStreamSerializationAllowed = 1;
    cfg.attrs = attr;
    cfg.numAttrs = 1;
    cudaError_t err = cudaLaunchKernelEx(&cfg, qlayer_kernel, xp, (float*)d_out, B);
    if (err != cudaSuccess) {
        // Fallback: plain launch (still correct; gridDepSync becomes a no-op).
        qlayer_kernel<<<grid, 256>>>(xp, (float*)d_out, B);
    }
}